// round 9
// baseline (speedup 1.0000x reference)
#include <cuda_runtime.h>
#include <cuda_fp16.h>
#include <math.h>
#include <stdint.h>

#define NN 50000
#define NE 640000
#define W 128
#define NCONV 6

// ---------------- scratch (device globals: no allocation allowed) ----------------
__device__ int   g_is64;
__device__ int   g_deg[NN];
__device__ float g_dis[NN];
__device__ int   g_rowptr[NN + 1];
__device__ int   g_fill[NN];
__device__ int   g_csr_src[NE];
__device__ float g_csr_w[NE];

// fp16 Chebyshev term buffers (NN rows x 128 halves = 16 uint4/row)
__device__ uint4 g_T1h[(size_t)NN * 16];
__device__ uint4 g_T2h[(size_t)NN * 16];
__device__ uint4 g_T3h[(size_t)NN * 16];
__device__ uint4 g_T4h[(size_t)NN * 16];
// fp32 layer activations
__device__ float g_HA[(size_t)NN * W];
__device__ float g_HB[(size_t)NN * W];

// telescoped last layer (fp32, tiny)
__device__ float g_U [(size_t)NN * 8];
__device__ float g_Y1[(size_t)NN * 8];
__device__ float g_Y2[(size_t)NN * 8];
__device__ float g_Y3[(size_t)NN * 8];
__device__ float g_Y4[(size_t)NN * 8];
__device__ float g_WT[5 * W];
__device__ float g_c0;

// ---------------- dtype detection ----------------
__global__ void detect_kernel(const int* __restrict__ ei) {
    __shared__ int any;
    if (threadIdx.x == 0) any = 0;
    __syncthreads();
    for (int i = threadIdx.x; i < 4096; i += blockDim.x)
        if (ei[2 * i + 1] != 0) any = 1;
    __syncthreads();
    if (threadIdx.x == 0) g_is64 = (any == 0) ? 1 : 0;
}

__device__ __forceinline__ int load_edge(const void* ei, long long idx, int is64) {
    if (is64) return (int)((const long long*)ei)[idx];
    return ((const int*)ei)[idx];
}

// ---------------- CSR build ----------------
__global__ void init_kernel() {
    int i = blockIdx.x * blockDim.x + threadIdx.x;
    if (i < NN) { g_deg[i] = 0; g_fill[i] = 0; }
}

__global__ void deg_kernel(const void* __restrict__ ei) {
    int e = blockIdx.x * blockDim.x + threadIdx.x;
    if (e >= NE) return;
    int is64 = g_is64;
    int d = load_edge(ei, (long long)NE + e, is64);
    atomicAdd(&g_deg[d], 1);
}

__global__ void scan_kernel() {   // also computes g_dis
    __shared__ int sums[1024];
    const int t = threadIdx.x;
    const int CH = (NN + 1023) / 1024;
    int begin = t * CH;
    int end = begin + CH; if (end > NN) end = NN;
    int s = 0;
    for (int i = begin; i < end; i++) {
        int d = g_deg[i];
        g_dis[i] = (d > 0) ? rsqrtf((float)d) : 0.0f;
        s += d;
    }
    sums[t] = s;
    __syncthreads();
    for (int off = 1; off < 1024; off <<= 1) {
        int v = (t >= off) ? sums[t - off] : 0;
        __syncthreads();
        sums[t] += v;
        __syncthreads();
    }
    int prefix = (t == 0) ? 0 : sums[t - 1];
    for (int i = begin; i < end; i++) {
        g_rowptr[i] = prefix;
        prefix += g_deg[i];
    }
    if (t == 1023) g_rowptr[NN] = sums[1023];
}

__global__ void fill_kernel(const void* __restrict__ ei) {
    int e = blockIdx.x * blockDim.x + threadIdx.x;
    if (e >= NE) return;
    int is64 = g_is64;
    int s = load_edge(ei, e, is64);
    int d = load_edge(ei, (long long)NE + e, is64);
    int pos = atomicAdd(&g_fill[d], 1);
    int idx = g_rowptr[d] + pos;
    g_csr_src[idx] = s;
    g_csr_w[idx]   = -g_dis[s] * g_dis[d];
}

#define PROP_BLOCKS 1184

// ---------------- T1 = L @ H  (fp32 gather -> fp16 out) -------------------------
__global__ void __launch_bounds__(256) prop32_16_kernel(
    const float* __restrict__ X, __half* __restrict__ out)
{
    const int lane = threadIdx.x & 31;
    const int warp0 = (blockIdx.x * blockDim.x + threadIdx.x) >> 5;
    const int wstride = (PROP_BLOCKS * 256) >> 5;
    const float4* X4 = (const float4*)X;

    for (int node = warp0; node < NN; node += wstride) {
        int start = g_rowptr[node];
        int end   = g_rowptr[node + 1];
        float4 acc = make_float4(0.f, 0.f, 0.f, 0.f);
        int i = start;
        for (; i + 1 < end; i += 2) {
            int s0 = g_csr_src[i];     float w0 = g_csr_w[i];
            int s1 = g_csr_src[i + 1]; float w1 = g_csr_w[i + 1];
            float4 v0 = X4[(size_t)s0 * 32 + lane];
            float4 v1 = X4[(size_t)s1 * 32 + lane];
            acc.x += w0 * v0.x; acc.y += w0 * v0.y; acc.z += w0 * v0.z; acc.w += w0 * v0.w;
            acc.x += w1 * v1.x; acc.y += w1 * v1.y; acc.z += w1 * v1.z; acc.w += w1 * v1.w;
        }
        if (i < end) {
            int s0 = g_csr_src[i]; float w0 = g_csr_w[i];
            float4 v0 = X4[(size_t)s0 * 32 + lane];
            acc.x += w0 * v0.x; acc.y += w0 * v0.y; acc.z += w0 * v0.z; acc.w += w0 * v0.w;
        }
        __half2 o0 = __floats2half2_rn(acc.x, acc.y);
        __half2 o1 = __floats2half2_rn(acc.z, acc.w);
        uint2 o; o.x = *(unsigned*)&o0; o.y = *(unsigned*)&o1;
        ((uint2*)out)[(size_t)node * 32 + lane] = o;
    }
}

// ---------------- T2 = 2 L @ T1 - H  (fp16 gather, fp32 prev, fp16 out) ---------
__global__ void __launch_bounds__(256) prop16_p32_kernel(
    const __half* __restrict__ X, const float* __restrict__ prev,
    __half* __restrict__ out)
{
    const int lane = threadIdx.x & 31;
    const int warp0 = (blockIdx.x * blockDim.x + threadIdx.x) >> 5;
    const int wstride = (PROP_BLOCKS * 256) >> 5;
    const uint2* X2 = (const uint2*)X;

    for (int node = warp0; node < NN; node += wstride) {
        int start = g_rowptr[node];
        int end   = g_rowptr[node + 1];
        float a0 = 0.f, a1 = 0.f, a2 = 0.f, a3 = 0.f;
        int i = start;
        for (; i + 1 < end; i += 2) {
            int s0 = g_csr_src[i];     float w0 = g_csr_w[i];
            int s1 = g_csr_src[i + 1]; float w1 = g_csr_w[i + 1];
            uint2 u0 = X2[(size_t)s0 * 32 + lane];
            uint2 u1 = X2[(size_t)s1 * 32 + lane];
            float2 f00 = __half22float2(*(__half2*)&u0.x);
            float2 f01 = __half22float2(*(__half2*)&u0.y);
            float2 f10 = __half22float2(*(__half2*)&u1.x);
            float2 f11 = __half22float2(*(__half2*)&u1.y);
            a0 = fmaf(w0, f00.x, a0); a1 = fmaf(w0, f00.y, a1);
            a2 = fmaf(w0, f01.x, a2); a3 = fmaf(w0, f01.y, a3);
            a0 = fmaf(w1, f10.x, a0); a1 = fmaf(w1, f10.y, a1);
            a2 = fmaf(w1, f11.x, a2); a3 = fmaf(w1, f11.y, a3);
        }
        if (i < end) {
            int s0 = g_csr_src[i]; float w0 = g_csr_w[i];
            uint2 u0 = X2[(size_t)s0 * 32 + lane];
            float2 f00 = __half22float2(*(__half2*)&u0.x);
            float2 f01 = __half22float2(*(__half2*)&u0.y);
            a0 = fmaf(w0, f00.x, a0); a1 = fmaf(w0, f00.y, a1);
            a2 = fmaf(w0, f01.x, a2); a3 = fmaf(w0, f01.y, a3);
        }
        float4 p = ((const float4*)prev)[(size_t)node * 32 + lane];
        __half2 o0 = __floats2half2_rn(2.f * a0 - p.x, 2.f * a1 - p.y);
        __half2 o1 = __floats2half2_rn(2.f * a2 - p.z, 2.f * a3 - p.w);
        uint2 o; o.x = *(unsigned*)&o0; o.y = *(unsigned*)&o1;
        ((uint2*)out)[(size_t)node * 32 + lane] = o;
    }
}

// ---------------- Tk = 2 L @ T(k-1) - T(k-2)  (all fp16) ------------------------
__global__ void __launch_bounds__(256) prop16_kernel(
    const __half* __restrict__ X, const __half* __restrict__ prev,
    __half* __restrict__ out)
{
    const int lane = threadIdx.x & 31;
    const int warp0 = (blockIdx.x * blockDim.x + threadIdx.x) >> 5;
    const int wstride = (PROP_BLOCKS * 256) >> 5;
    const uint2* X2 = (const uint2*)X;

    for (int node = warp0; node < NN; node += wstride) {
        int start = g_rowptr[node];
        int end   = g_rowptr[node + 1];
        float a0 = 0.f, a1 = 0.f, a2 = 0.f, a3 = 0.f;
        int i = start;
        for (; i + 1 < end; i += 2) {
            int s0 = g_csr_src[i];     float w0 = g_csr_w[i];
            int s1 = g_csr_src[i + 1]; float w1 = g_csr_w[i + 1];
            uint2 u0 = X2[(size_t)s0 * 32 + lane];
            uint2 u1 = X2[(size_t)s1 * 32 + lane];
            float2 f00 = __half22float2(*(__half2*)&u0.x);
            float2 f01 = __half22float2(*(__half2*)&u0.y);
            float2 f10 = __half22float2(*(__half2*)&u1.x);
            float2 f11 = __half22float2(*(__half2*)&u1.y);
            a0 = fmaf(w0, f00.x, a0); a1 = fmaf(w0, f00.y, a1);
            a2 = fmaf(w0, f01.x, a2); a3 = fmaf(w0, f01.y, a3);
            a0 = fmaf(w1, f10.x, a0); a1 = fmaf(w1, f10.y, a1);
            a2 = fmaf(w1, f11.x, a2); a3 = fmaf(w1, f11.y, a3);
        }
        if (i < end) {
            int s0 = g_csr_src[i]; float w0 = g_csr_w[i];
            uint2 u0 = X2[(size_t)s0 * 32 + lane];
            float2 f00 = __half22float2(*(__half2*)&u0.x);
            float2 f01 = __half22float2(*(__half2*)&u0.y);
            a0 = fmaf(w0, f00.x, a0); a1 = fmaf(w0, f00.y, a1);
            a2 = fmaf(w0, f01.x, a2); a3 = fmaf(w0, f01.y, a3);
        }
        uint2 pv = ((const uint2*)prev)[(size_t)node * 32 + lane];
        float2 p0 = __half22float2(*(__half2*)&pv.x);
        float2 p1 = __half22float2(*(__half2*)&pv.y);
        __half2 o0 = __floats2half2_rn(2.f * a0 - p0.x, 2.f * a1 - p0.y);
        __half2 o1 = __floats2half2_rn(2.f * a2 - p1.x, 2.f * a3 - p1.y);
        uint2 o; o.x = *(unsigned*)&o0; o.y = *(unsigned*)&o1;
        ((uint2*)out)[(size_t)node * 32 + lane] = o;
    }
}

// ---------------- fused GEMM: term0 fp32 A (split, 3 passes), terms 1-4 fp16 A --
struct PtrMix { const float* a0; const __half* a[4]; };

#define KPAD 24

__device__ __forceinline__ void mma16816(float c[4], const unsigned a[4], const unsigned b0, const unsigned b1) {
    asm volatile(
        "mma.sync.aligned.m16n8k16.row.col.f32.f16.f16.f32 "
        "{%0,%1,%2,%3}, {%4,%5,%6,%7}, {%8,%9}, {%0,%1,%2,%3};"
        : "+f"(c[0]), "+f"(c[1]), "+f"(c[2]), "+f"(c[3])
        : "r"(a[0]), "r"(a[1]), "r"(a[2]), "r"(a[3]), "r"(b0), "r"(b1));
}

__device__ __forceinline__ void ldm4(unsigned r[4], unsigned addr) {
    asm volatile("ldmatrix.sync.aligned.m8n8.x4.shared.b16 {%0,%1,%2,%3}, [%4];"
        : "=r"(r[0]), "=r"(r[1]), "=r"(r[2]), "=r"(r[3]) : "r"(addr));
}

__global__ void __launch_bounds__(256) gemm5x_kernel(
    PtrMix T, const float* __restrict__ Wc, const float* __restrict__ bias,
    float* __restrict__ out, int relu)
{
    __shared__ __half Ah[2][128][KPAD];
    __shared__ __half Al[2][128][KPAD];
    __shared__ __half Bh[2][128][KPAD];   // [n][k]
    __shared__ __half Bl[2][128][KPAD];

    const int tid  = threadIdx.x;
    const int lane = tid & 31;
    const int wid  = tid >> 5;
    const int warpM = wid & 1;
    const int warpN = wid >> 1;
    const int m0 = blockIdx.x * 128;

    const int arow = tid >> 1;
    const int akk  = (tid & 1) * 8;
    const int bn = tid & 127;
    const int bk = (tid >> 7) * 8;

    float acc[4][4][4];
#pragma unroll
    for (int i = 0; i < 4; i++)
#pragma unroll
        for (int j = 0; j < 4; j++)
#pragma unroll
            for (int q = 0; q < 4; q++) acc[i][j][q] = 0.f;

    float pa[8];
    uint4 pah;
    float pb[8];

    const int a_mrow = (lane & 7) + ((lane & 8) ? 8 : 0);
    const int a_koff = (lane & 16) ? 8 : 0;
    const int b_nrow = (lane & 7) + ((lane & 16) ? 8 : 0);
    const int b_koff = (lane & 8) ? 8 : 0;

    auto loadG = [&](int kc) {
        const int t  = kc >> 3;
        const int kk = (kc & 7) * 16;
        int m = m0 + arow;
        if (t == 0) {
            if (m < NN) {
                const float4 v0 = *(const float4*)(T.a0 + (size_t)m * W + kk + akk);
                const float4 v1 = *(const float4*)(T.a0 + (size_t)m * W + kk + akk + 4);
                pa[0] = v0.x; pa[1] = v0.y; pa[2] = v0.z; pa[3] = v0.w;
                pa[4] = v1.x; pa[5] = v1.y; pa[6] = v1.z; pa[7] = v1.w;
            } else {
#pragma unroll
                for (int j = 0; j < 8; j++) pa[j] = 0.f;
            }
        } else {
            if (m < NN) {
                const uint4* A4 = (const uint4*)T.a[t - 1];
                pah = A4[(size_t)m * 16 + (kk >> 3) + (tid & 1)];
            } else {
                pah = make_uint4(0, 0, 0, 0);
            }
        }
        const float* Wt = Wc + t * (W * W);
#pragma unroll
        for (int j = 0; j < 8; j++) pb[j] = Wt[(kk + bk + j) * W + bn];
    };

    auto storeS = [&](int buf, bool isf32) {
        if (isf32) {
            union { __half2 h2[4]; uint4 u; } ph, pl;
#pragma unroll
            for (int j = 0; j < 4; j++) {
                __half h0 = __float2half_rn(pa[2 * j]);
                __half h1 = __float2half_rn(pa[2 * j + 1]);
                __half l0 = __float2half_rn(pa[2 * j] - __half2float(h0));
                __half l1 = __float2half_rn(pa[2 * j + 1] - __half2float(h1));
                ph.h2[j] = __halves2half2(h0, h1);
                pl.h2[j] = __halves2half2(l0, l1);
            }
            *(uint4*)&Ah[buf][arow][akk] = ph.u;
            *(uint4*)&Al[buf][arow][akk] = pl.u;
        } else {
            *(uint4*)&Ah[buf][arow][akk] = pah;
        }
        union { __half2 h2[4]; uint4 u; } qh, ql;
#pragma unroll
        for (int j = 0; j < 4; j++) {
            __half h0 = __float2half_rn(pb[2 * j]);
            __half h1 = __float2half_rn(pb[2 * j + 1]);
            __half l0 = __float2half_rn(pb[2 * j] - __half2float(h0));
            __half l1 = __float2half_rn(pb[2 * j + 1] - __half2float(h1));
            qh.h2[j] = __halves2half2(h0, h1);
            ql.h2[j] = __halves2half2(l0, l1);
        }
        *(uint4*)&Bh[buf][bn][bk] = qh.u;
        *(uint4*)&Bl[buf][bn][bk] = ql.u;
    };

    loadG(0);
    storeS(0, true);

    for (int kc = 0; kc < 40; kc++) {
        __syncthreads();
        const int cur = kc & 1;
        const bool is0 = (kc < 8);
        const bool more = (kc + 1 < 40);
        if (more) loadG(kc + 1);

        unsigned fah[4][4], fal[4][4];
        unsigned fbh[8], fbl[8];
#pragma unroll
        for (int mt = 0; mt < 4; mt++) {
            int row = warpM * 64 + mt * 16 + a_mrow;
            unsigned ah = (unsigned)__cvta_generic_to_shared(&Ah[cur][row][a_koff]);
            ldm4(fah[mt], ah);
            if (is0) {
                unsigned al = (unsigned)__cvta_generic_to_shared(&Al[cur][row][a_koff]);
                ldm4(fal[mt], al);
            }
        }
        {
            int n0 = warpN * 32 + b_nrow;
            int n1 = warpN * 32 + 16 + b_nrow;
            unsigned bh0 = (unsigned)__cvta_generic_to_shared(&Bh[cur][n0][b_koff]);
            unsigned bh1 = (unsigned)__cvta_generic_to_shared(&Bh[cur][n1][b_koff]);
            unsigned bl0 = (unsigned)__cvta_generic_to_shared(&Bl[cur][n0][b_koff]);
            unsigned bl1 = (unsigned)__cvta_generic_to_shared(&Bl[cur][n1][b_koff]);
            ldm4(&fbh[0], bh0);
            ldm4(&fbh[4], bh1);
            ldm4(&fbl[0], bl0);
            ldm4(&fbl[4], bl1);
        }

#pragma unroll
        for (int mt = 0; mt < 4; mt++) {
#pragma unroll
            for (int nt = 0; nt < 4; nt++) {
                mma16816(acc[mt][nt], fah[mt], fbh[2 * nt], fbh[2 * nt + 1]);
                mma16816(acc[mt][nt], fah[mt], fbl[2 * nt], fbl[2 * nt + 1]);
                if (is0)
                    mma16816(acc[mt][nt], fal[mt], fbh[2 * nt], fbh[2 * nt + 1]);
            }
        }

        if (more) storeS((kc + 1) & 1, (kc + 1) < 8);
    }

    // epilogue: fp32 out + bias (+relu)
    const int crow = lane >> 2;
    const int ccol = (lane & 3) * 2;
#pragma unroll
    for (int mt = 0; mt < 4; mt++) {
        int r = m0 + warpM * 64 + mt * 16 + crow;
#pragma unroll
        for (int nt = 0; nt < 4; nt++) {
            int c = warpN * 32 + nt * 8 + ccol;
            float b0 = bias[c], b1 = bias[c + 1];
            float v0 = acc[mt][nt][0] + b0;
            float v1 = acc[mt][nt][1] + b1;
            float v2 = acc[mt][nt][2] + b0;
            float v3 = acc[mt][nt][3] + b1;
            if (relu) {
                v0 = fmaxf(v0, 0.f); v1 = fmaxf(v1, 0.f);
                v2 = fmaxf(v2, 0.f); v3 = fmaxf(v3, 0.f);
            }
            if (r < NN)     *(float2*)(out + (size_t)r * W + c)       = make_float2(v0, v1);
            if (r + 8 < NN) *(float2*)(out + (size_t)(r + 8) * W + c) = make_float2(v2, v3);
        }
    }
}

// ---------------- last-layer telescope ----------------
__global__ void wtilde_kernel(const float* __restrict__ W5,
                              const float* __restrict__ lw)
{
    int idx = blockIdx.x * blockDim.x + threadIdx.x;
    if (idx >= 5 * W) return;
    const float* row = W5 + (size_t)idx * W;
    float s = 0.f;
    for (int o = 0; o < W; o++) s += row[o] * lw[o];
    g_WT[idx] = s;
}

__global__ void const_kernel(const float* __restrict__ cb,
                             const float* __restrict__ lw,
                             const float* __restrict__ lb)
{
    int lane = threadIdx.x & 31;
    float4 b = ((const float4*)cb)[lane];
    float4 w = ((const float4*)lw)[lane];
    float s = b.x * w.x + b.y * w.y + b.z * w.z + b.w * w.w;
#pragma unroll
    for (int off = 16; off > 0; off >>= 1)
        s += __shfl_xor_sync(0xffffffffu, s, off);
    if (lane == 0) g_c0 = s + lb[0];
}

__global__ void __launch_bounds__(256) u_kernel(
    const float* __restrict__ H, float* __restrict__ U)
{
    __shared__ float wt[5][W];
    for (int i = threadIdx.x; i < 5 * W; i += blockDim.x)
        wt[i / W][i % W] = g_WT[i];
    __syncthreads();

    int warp = (blockIdx.x * blockDim.x + threadIdx.x) >> 5;
    int lane = threadIdx.x & 31;
    if (warp >= NN) return;
    float4 hv = ((const float4*)H)[(size_t)warp * 32 + lane];
    float s[5];
#pragma unroll
    for (int k = 0; k < 5; k++) {
        float4 wv = ((const float4*)wt[k])[lane];
        float p = hv.x * wv.x + hv.y * wv.y + hv.z * wv.z + hv.w * wv.w;
#pragma unroll
        for (int off = 16; off > 0; off >>= 1)
            p += __shfl_xor_sync(0xffffffffu, p, off);
        s[k] = p;
    }
    if (lane == 0) {
        float* o = U + (size_t)warp * 8;
        o[0] = s[0]; o[1] = s[1]; o[2] = s[2]; o[3] = s[3]; o[4] = s[4];
        o[5] = 0.f;  o[6] = 0.f;  o[7] = 0.f;
    }
}

__global__ void __launch_bounds__(256) prop8_kernel(
    const float* __restrict__ U, const float* __restrict__ prev,
    float* __restrict__ out, int mode)
{
    const int l = threadIdx.x & 7;
    const int g0 = (blockIdx.x * blockDim.x + threadIdx.x) >> 3;
    const int gstride = (PROP_BLOCKS * 256) >> 3;
    for (int node = g0; node < NN; node += gstride) {
        int start = g_rowptr[node];
        int end   = g_rowptr[node + 1];
        float acc = 0.f;
        for (int i = start; i < end; i++) {
            int s = g_csr_src[i];
            float w = g_csr_w[i];
            acc += w * U[s * 8 + l];
        }
        float r = mode ? (2.f * acc - prev[node * 8 + l]) : acc;
        out[node * 8 + l] = r;
    }
}

__global__ void combine_kernel(
    const float* __restrict__ Y0, const float* __restrict__ Y1,
    const float* __restrict__ Y2, const float* __restrict__ Y3,
    const float* __restrict__ Y4, float* __restrict__ out)
{
    int j = blockIdx.x * blockDim.x + threadIdx.x;
    if (j >= NN) return;
    float s = Y0[(size_t)j * 8 + 0] + Y1[(size_t)j * 8 + 1] + Y2[(size_t)j * 8 + 2]
            + Y3[(size_t)j * 8 + 3] + Y4[(size_t)j * 8 + 4] + g_c0;
    out[j] = s;
}

// ---------------- launcher ----------------
extern "C" void kernel_launch(void* const* d_in, const int* in_sizes, int n_in,
                              void* d_out, int out_size)
{
    const float* x      = (const float*)d_in[0];
    const void*  ei     = d_in[1];
    const float* conv_w = (const float*)d_in[2];
    const float* conv_b = (const float*)d_in[3];
    const float* lin_w  = (const float*)d_in[4];
    const float* lin_b  = (const float*)d_in[5];
    float* out = (float*)d_out;

    __half *pT1, *pT2, *pT3, *pT4;
    float *pHA, *pHB, *pU, *pY1, *pY2, *pY3, *pY4;
    cudaGetSymbolAddress((void**)&pT1, g_T1h);
    cudaGetSymbolAddress((void**)&pT2, g_T2h);
    cudaGetSymbolAddress((void**)&pT3, g_T3h);
    cudaGetSymbolAddress((void**)&pT4, g_T4h);
    cudaGetSymbolAddress((void**)&pHA, g_HA);
    cudaGetSymbolAddress((void**)&pHB, g_HB);
    cudaGetSymbolAddress((void**)&pU, g_U);
    cudaGetSymbolAddress((void**)&pY1, g_Y1);
    cudaGetSymbolAddress((void**)&pY2, g_Y2);
    cudaGetSymbolAddress((void**)&pY3, g_Y3);
    cudaGetSymbolAddress((void**)&pY4, g_Y4);

    detect_kernel<<<1, 256>>>((const int*)ei);
    init_kernel<<<(NN + 255) / 256, 256>>>();
    deg_kernel<<<(NE + 255) / 256, 256>>>(ei);
    scan_kernel<<<1, 1024>>>();
    fill_kernel<<<(NE + 255) / 256, 256>>>(ei);
    wtilde_kernel<<<3, 256>>>(conv_w + (size_t)5 * 5 * W * W, lin_w);
    const_kernel<<<1, 32>>>(conv_b + 5 * W, lin_w, lin_b);

    const int GG = (NN + 127) / 128;

    const float* Hin = x;
    float* Hout = pHA;
    for (int l = 0; l < 5; l++) {
        prop32_16_kernel<<<PROP_BLOCKS, 256>>>(Hin, pT1);
        prop16_p32_kernel<<<PROP_BLOCKS, 256>>>(pT1, Hin, pT2);
        prop16_kernel<<<PROP_BLOCKS, 256>>>(pT2, pT1, pT3);
        prop16_kernel<<<PROP_BLOCKS, 256>>>(pT3, pT2, pT4);
        PtrMix T;
        T.a0 = Hin; T.a[0] = pT1; T.a[1] = pT2; T.a[2] = pT3; T.a[3] = pT4;
        gemm5x_kernel<<<GG, 256>>>(T, conv_w + (size_t)l * 5 * W * W,
                                   conv_b + l * W, Hout, 1);
        Hin = Hout;
        Hout = (Hout == pHA) ? pHB : pHA;
    }

    // telescoped last layer (fp32 path)
    u_kernel<<<(NN + 7) / 8, 256>>>(Hin, pU);
    prop8_kernel<<<PROP_BLOCKS, 256>>>(pU, nullptr, pY1, 0);
    prop8_kernel<<<PROP_BLOCKS, 256>>>(pY1, pU, pY2, 1);
    prop8_kernel<<<PROP_BLOCKS, 256>>>(pY2, pY1, pY3, 1);
    prop8_kernel<<<PROP_BLOCKS, 256>>>(pY3, pY2, pY4, 1);
    combine_kernel<<<(NN + 255) / 256, 256>>>(pU, pY1, pY2, pY3, pY4, out);
}

// round 10
// speedup vs baseline: 1.2055x; 1.2055x over previous
#include <cuda_runtime.h>
#include <cuda_fp16.h>
#include <math.h>

#define NN 50000
#define NE 640000
#define W 128
#define NCONV 6
#define NBLK 196   // (NN+255)/256

// ---------------- scratch (device globals: no allocation allowed) ----------------
__device__ int   g_is64;
__device__ int   g_deg[NN];
__device__ float g_dis[NN];
__device__ int   g_rowptr[NN + 1];
__device__ int   g_fill[NN];
__device__ int   g_csr_src[NE];
__device__ float g_csr_w[NE];
__device__ int   g_bsum[NBLK];
__device__ int   g_boff[NBLK];

__device__ float g_T1[(size_t)NN * W];
__device__ float g_T2[(size_t)NN * W];
__device__ float g_T3[(size_t)NN * W];
__device__ float g_T4[(size_t)NN * W];
__device__ float g_HA[(size_t)NN * W];
__device__ float g_HB[(size_t)NN * W];

__device__ float g_U [(size_t)NN * 8];
__device__ float g_Y1[(size_t)NN * 8];
__device__ float g_Y2[(size_t)NN * 8];
__device__ float g_Y3[(size_t)NN * 8];
__device__ float g_Y4[(size_t)NN * 8];
__device__ float g_WT[5 * W];
__device__ float g_c0;

// ---------------- dtype detection ----------------
__global__ void detect_kernel(const int* __restrict__ ei) {
    __shared__ int any;
    if (threadIdx.x == 0) any = 0;
    __syncthreads();
    for (int i = threadIdx.x; i < 4096; i += blockDim.x)
        if (ei[2 * i + 1] != 0) any = 1;
    __syncthreads();
    if (threadIdx.x == 0) g_is64 = (any == 0) ? 1 : 0;
}

__device__ __forceinline__ int load_edge(const void* ei, long long idx, int is64) {
    if (is64) return (int)((const long long*)ei)[idx];
    return ((const int*)ei)[idx];
}

// ---------------- CSR build ----------------
__global__ void init_kernel() {
    int i = blockIdx.x * blockDim.x + threadIdx.x;
    if (i < NN) { g_deg[i] = 0; g_fill[i] = 0; }
}

__global__ void deg_kernel(const void* __restrict__ ei) {
    int e = blockIdx.x * blockDim.x + threadIdx.x;
    if (e >= NE) return;
    int is64 = g_is64;
    int d = load_edge(ei, (long long)NE + e, is64);
    atomicAdd(&g_deg[d], 1);
}

// phase 1: per-block degree sums (coalesced) + d^-1/2
__global__ void dsum_kernel() {
    __shared__ int sdata[256];
    int t = threadIdx.x;
    int i = blockIdx.x * 256 + t;
    int d = (i < NN) ? g_deg[i] : 0;
    if (i < NN) g_dis[i] = (d > 0) ? rsqrtf((float)d) : 0.0f;
    sdata[t] = d;
    __syncthreads();
    for (int s = 128; s > 0; s >>= 1) {
        if (t < s) sdata[t] += sdata[t + s];
        __syncthreads();
    }
    if (t == 0) g_bsum[blockIdx.x] = sdata[0];
}

// phase 2: 1-block scan of 196 block sums -> exclusive block offsets
__global__ void bscan_kernel() {
    __shared__ int s[256];
    int t = threadIdx.x;
    int v = (t < NBLK) ? g_bsum[t] : 0;
    s[t] = v;
    __syncthreads();
    for (int off = 1; off < 256; off <<= 1) {
        int u = (t >= off) ? s[t - off] : 0;
        __syncthreads();
        s[t] += u;
        __syncthreads();
    }
    if (t < NBLK) g_boff[t] = (t == 0) ? 0 : s[t - 1];
}

// phase 3: block-local inclusive scan + block offset -> exclusive rowptr
__global__ void rowptr_kernel() {
    __shared__ int s[256];
    int t = threadIdx.x;
    int i = blockIdx.x * 256 + t;
    int d = (i < NN) ? g_deg[i] : 0;
    s[t] = d;
    __syncthreads();
    for (int off = 1; off < 256; off <<= 1) {
        int u = (t >= off) ? s[t - off] : 0;
        __syncthreads();
        s[t] += u;
        __syncthreads();
    }
    if (i < NN) g_rowptr[i] = g_boff[blockIdx.x] + s[t] - d;
    if (i == NN - 1) g_rowptr[NN] = NE;
}

__global__ void fill_kernel(const void* __restrict__ ei) {
    int e = blockIdx.x * blockDim.x + threadIdx.x;
    if (e >= NE) return;
    int is64 = g_is64;
    int s = load_edge(ei, e, is64);
    int d = load_edge(ei, (long long)NE + e, is64);
    int pos = atomicAdd(&g_fill[d], 1);
    int idx = g_rowptr[d] + pos;
    g_csr_src[idx] = s;
    g_csr_w[idx]   = -g_dis[s] * g_dis[d];
}

// ---------------- propagate: persistent grid-stride (fp32) ---------------------
#define PROP_BLOCKS 1184   // 148 SMs * 8 CTAs

__global__ void __launch_bounds__(256) propagate_kernel(
    const float* __restrict__ X, const float* __restrict__ prev,
    float* __restrict__ out, int mode)
{
    const int lane = threadIdx.x & 31;
    const int warp0 = (blockIdx.x * blockDim.x + threadIdx.x) >> 5;
    const int wstride = (PROP_BLOCKS * 256) >> 5;   // 9472
    const float4* X4 = (const float4*)X;

    for (int node = warp0; node < NN; node += wstride) {
        int start = g_rowptr[node];
        int end   = g_rowptr[node + 1];
        float4 acc = make_float4(0.f, 0.f, 0.f, 0.f);
        int i = start;
        for (; i + 1 < end; i += 2) {
            int s0 = g_csr_src[i];     float w0 = g_csr_w[i];
            int s1 = g_csr_src[i + 1]; float w1 = g_csr_w[i + 1];
            float4 v0 = X4[(size_t)s0 * 32 + lane];
            float4 v1 = X4[(size_t)s1 * 32 + lane];
            acc.x += w0 * v0.x; acc.y += w0 * v0.y; acc.z += w0 * v0.z; acc.w += w0 * v0.w;
            acc.x += w1 * v1.x; acc.y += w1 * v1.y; acc.z += w1 * v1.z; acc.w += w1 * v1.w;
        }
        if (i < end) {
            int s0 = g_csr_src[i]; float w0 = g_csr_w[i];
            float4 v0 = X4[(size_t)s0 * 32 + lane];
            acc.x += w0 * v0.x; acc.y += w0 * v0.y; acc.z += w0 * v0.z; acc.w += w0 * v0.w;
        }
        float4 r;
        if (mode) {
            float4 p = ((const float4*)prev)[(size_t)node * 32 + lane];
            r.x = 2.f * acc.x - p.x; r.y = 2.f * acc.y - p.y;
            r.z = 2.f * acc.z - p.z; r.w = 2.f * acc.w - p.w;
        } else {
            r = acc;
        }
        ((float4*)out)[(size_t)node * 32 + lane] = r;
    }
}

// ---------------- tensor-core fused 5-term GEMM (split-fp16, fp32-grade) --------
struct Ptr5 { const float* p[5]; };

#define KPAD 24

__device__ __forceinline__ void mma16816(float c[4], const unsigned a[4], const unsigned b0, const unsigned b1) {
    asm volatile(
        "mma.sync.aligned.m16n8k16.row.col.f32.f16.f16.f32 "
        "{%0,%1,%2,%3}, {%4,%5,%6,%7}, {%8,%9}, {%0,%1,%2,%3};"
        : "+f"(c[0]), "+f"(c[1]), "+f"(c[2]), "+f"(c[3])
        : "r"(a[0]), "r"(a[1]), "r"(a[2]), "r"(a[3]), "r"(b0), "r"(b1));
}

__device__ __forceinline__ void ldm4(unsigned r[4], unsigned addr) {
    asm volatile("ldmatrix.sync.aligned.m8n8.x4.shared.b16 {%0,%1,%2,%3}, [%4];"
        : "=r"(r[0]), "=r"(r[1]), "=r"(r[2]), "=r"(r[3]) : "r"(addr));
}

__global__ void __launch_bounds__(256) gemm5_mma_kernel(
    Ptr5 T, const float* __restrict__ Wc, const float* __restrict__ bias,
    float* __restrict__ out, int relu)
{
    __shared__ __half Ah[2][128][KPAD];
    __shared__ __half Al[2][128][KPAD];
    __shared__ __half Bh[2][128][KPAD];   // [n][k]
    __shared__ __half Bl[2][128][KPAD];

    const int tid  = threadIdx.x;
    const int lane = tid & 31;
    const int wid  = tid >> 5;
    const int warpM = wid & 1;
    const int warpN = wid >> 1;
    const int m0 = blockIdx.x * 128;

    const int arow = tid >> 1;
    const int akk  = (tid & 1) * 8;
    const int bn = tid & 127;
    const int bk = (tid >> 7) * 8;

    float acc[4][4][4];
#pragma unroll
    for (int i = 0; i < 4; i++)
#pragma unroll
        for (int j = 0; j < 4; j++)
#pragma unroll
            for (int q = 0; q < 4; q++) acc[i][j][q] = 0.f;

    float pa[8], pb[8];

    const int a_mrow = (lane & 7) + ((lane & 8) ? 8 : 0);
    const int a_koff = (lane & 16) ? 8 : 0;
    const int b_nrow = (lane & 7) + ((lane & 16) ? 8 : 0);
    const int b_koff = (lane & 8) ? 8 : 0;

    auto loadG = [&](int kc) {
        const int t  = kc >> 3;
        const int kk = (kc & 7) * 16;
        const float* A = T.p[t];
        int m = m0 + arow;
        if (m < NN) {
            const float4 v0 = *(const float4*)(A + (size_t)m * W + kk + akk);
            const float4 v1 = *(const float4*)(A + (size_t)m * W + kk + akk + 4);
            pa[0] = v0.x; pa[1] = v0.y; pa[2] = v0.z; pa[3] = v0.w;
            pa[4] = v1.x; pa[5] = v1.y; pa[6] = v1.z; pa[7] = v1.w;
        } else {
#pragma unroll
            for (int j = 0; j < 8; j++) pa[j] = 0.f;
        }
        const float* Wt = Wc + t * (W * W);
#pragma unroll
        for (int j = 0; j < 8; j++) pb[j] = Wt[(kk + bk + j) * W + bn];
    };

    auto storeS = [&](int buf) {
        union { __half2 h2[4]; uint4 u; } ph, pl;
#pragma unroll
        for (int j = 0; j < 4; j++) {
            __half h0 = __float2half_rn(pa[2 * j]);
            __half h1 = __float2half_rn(pa[2 * j + 1]);
            __half l0 = __float2half_rn(pa[2 * j] - __half2float(h0));
            __half l1 = __float2half_rn(pa[2 * j + 1] - __half2float(h1));
            ph.h2[j] = __halves2half2(h0, h1);
            pl.h2[j] = __halves2half2(l0, l1);
        }
        *(uint4*)&Ah[buf][arow][akk] = ph.u;
        *(uint4*)&Al[buf][arow][akk] = pl.u;
#pragma unroll
        for (int j = 0; j < 4; j++) {
            __half h0 = __float2half_rn(pb[2 * j]);
            __half h1 = __float2half_rn(pb[2 * j + 1]);
            __half l0 = __float2half_rn(pb[2 * j] - __half2float(h0));
            __half l1 = __float2half_rn(pb[2 * j + 1] - __half2float(h1));
            ph.h2[j] = __halves2half2(h0, h1);
            pl.h2[j] = __halves2half2(l0, l1);
        }
        *(uint4*)&Bh[buf][bn][bk] = ph.u;
        *(uint4*)&Bl[buf][bn][bk] = pl.u;
    };

    loadG(0);
    storeS(0);

    for (int kc = 0; kc < 40; kc++) {
        __syncthreads();
        const int cur = kc & 1;
        const bool more = (kc + 1 < 40);
        if (more) loadG(kc + 1);

        unsigned fah[4][4], fal[4][4];
        unsigned fbh[8], fbl[8];
#pragma unroll
        for (int mt = 0; mt < 4; mt++) {
            int row = warpM * 64 + mt * 16 + a_mrow;
            unsigned ah = (unsigned)__cvta_generic_to_shared(&Ah[cur][row][a_koff]);
            unsigned al = (unsigned)__cvta_generic_to_shared(&Al[cur][row][a_koff]);
            ldm4(fah[mt], ah);
            ldm4(fal[mt], al);
        }
        {
            int n0 = warpN * 32 + b_nrow;
            int n1 = warpN * 32 + 16 + b_nrow;
            unsigned bh0 = (unsigned)__cvta_generic_to_shared(&Bh[cur][n0][b_koff]);
            unsigned bh1 = (unsigned)__cvta_generic_to_shared(&Bh[cur][n1][b_koff]);
            unsigned bl0 = (unsigned)__cvta_generic_to_shared(&Bl[cur][n0][b_koff]);
            unsigned bl1 = (unsigned)__cvta_generic_to_shared(&Bl[cur][n1][b_koff]);
            ldm4(&fbh[0], bh0);
            ldm4(&fbh[4], bh1);
            ldm4(&fbl[0], bl0);
            ldm4(&fbl[4], bl1);
        }

#pragma unroll
        for (int mt = 0; mt < 4; mt++) {
#pragma unroll
            for (int nt = 0; nt < 4; nt++) {
                mma16816(acc[mt][nt], fah[mt], fbh[2 * nt], fbh[2 * nt + 1]);
                mma16816(acc[mt][nt], fah[mt], fbl[2 * nt], fbl[2 * nt + 1]);
                mma16816(acc[mt][nt], fal[mt], fbh[2 * nt], fbh[2 * nt + 1]);
            }
        }

        if (more) storeS((kc + 1) & 1);
    }

    const int crow = lane >> 2;
    const int ccol = (lane & 3) * 2;
#pragma unroll
    for (int mt = 0; mt < 4; mt++) {
        int r = m0 + warpM * 64 + mt * 16 + crow;
#pragma unroll
        for (int nt = 0; nt < 4; nt++) {
            int c = warpN * 32 + nt * 8 + ccol;
            float b0 = bias[c], b1 = bias[c + 1];
            float v0 = acc[mt][nt][0] + b0;
            float v1 = acc[mt][nt][1] + b1;
            float v2 = acc[mt][nt][2] + b0;
            float v3 = acc[mt][nt][3] + b1;
            if (relu) {
                v0 = fmaxf(v0, 0.f); v1 = fmaxf(v1, 0.f);
                v2 = fmaxf(v2, 0.f); v3 = fmaxf(v3, 0.f);
            }
            if (r < NN)     *(float2*)(out + (size_t)r * W + c)       = make_float2(v0, v1);
            if (r + 8 < NN) *(float2*)(out + (size_t)(r + 8) * W + c) = make_float2(v2, v3);
        }
    }
}

// ---------------- last-layer telescope ----------------
__global__ void wtilde_kernel(const float* __restrict__ W5,
                              const float* __restrict__ lw)
{
    int idx = blockIdx.x * blockDim.x + threadIdx.x;
    if (idx >= 5 * W) return;
    const float* row = W5 + (size_t)idx * W;
    float s = 0.f;
    for (int o = 0; o < W; o++) s += row[o] * lw[o];
    g_WT[idx] = s;
}

__global__ void const_kernel(const float* __restrict__ cb,
                             const float* __restrict__ lw,
                             const float* __restrict__ lb)
{
    int lane = threadIdx.x & 31;
    float4 b = ((const float4*)cb)[lane];
    float4 w = ((const float4*)lw)[lane];
    float s = b.x * w.x + b.y * w.y + b.z * w.z + b.w * w.w;
#pragma unroll
    for (int off = 16; off > 0; off >>= 1)
        s += __shfl_xor_sync(0xffffffffu, s, off);
    if (lane == 0) g_c0 = s + lb[0];
}

__global__ void __launch_bounds__(256) u_kernel(
    const float* __restrict__ H, float* __restrict__ U)
{
    __shared__ float wt[5][W];
    for (int i = threadIdx.x; i < 5 * W; i += blockDim.x)
        wt[i / W][i % W] = g_WT[i];
    __syncthreads();

    int warp = (blockIdx.x * blockDim.x + threadIdx.x) >> 5;
    int lane = threadIdx.x & 31;
    if (warp >= NN) return;
    float4 hv = ((const float4*)H)[(size_t)warp * 32 + lane];
    float s[5];
#pragma unroll
    for (int k = 0; k < 5; k++) {
        float4 wv = ((const float4*)wt[k])[lane];
        float p = hv.x * wv.x + hv.y * wv.y + hv.z * wv.z + hv.w * wv.w;
#pragma unroll
        for (int off = 16; off > 0; off >>= 1)
            p += __shfl_xor_sync(0xffffffffu, p, off);
        s[k] = p;
    }
    if (lane == 0) {
        float* o = U + (size_t)warp * 8;
        o[0] = s[0]; o[1] = s[1]; o[2] = s[2]; o[3] = s[3]; o[4] = s[4];
        o[5] = 0.f;  o[6] = 0.f;  o[7] = 0.f;
    }
}

__global__ void __launch_bounds__(256) prop8_kernel(
    const float* __restrict__ U, const float* __restrict__ prev,
    float* __restrict__ out, int mode)
{
    const int l = threadIdx.x & 7;
    const int g0 = (blockIdx.x * blockDim.x + threadIdx.x) >> 3;
    const int gstride = (PROP_BLOCKS * 256) >> 3;
    for (int node = g0; node < NN; node += gstride) {
        int start = g_rowptr[node];
        int end   = g_rowptr[node + 1];
        float acc = 0.f;
        for (int i = start; i < end; i++) {
            int s = g_csr_src[i];
            float w = g_csr_w[i];
            acc += w * U[s * 8 + l];
        }
        float r = mode ? (2.f * acc - prev[node * 8 + l]) : acc;
        out[node * 8 + l] = r;
    }
}

__global__ void combine_kernel(
    const float* __restrict__ Y0, const float* __restrict__ Y1,
    const float* __restrict__ Y2, const float* __restrict__ Y3,
    const float* __restrict__ Y4, float* __restrict__ out)
{
    int j = blockIdx.x * blockDim.x + threadIdx.x;
    if (j >= NN) return;
    float s = Y0[(size_t)j * 8 + 0] + Y1[(size_t)j * 8 + 1] + Y2[(size_t)j * 8 + 2]
            + Y3[(size_t)j * 8 + 3] + Y4[(size_t)j * 8 + 4] + g_c0;
    out[j] = s;
}

// ---------------- launcher ----------------
extern "C" void kernel_launch(void* const* d_in, const int* in_sizes, int n_in,
                              void* d_out, int out_size)
{
    const float* x      = (const float*)d_in[0];
    const void*  ei     = d_in[1];
    const float* conv_w = (const float*)d_in[2];
    const float* conv_b = (const float*)d_in[3];
    const float* lin_w  = (const float*)d_in[4];
    const float* lin_b  = (const float*)d_in[5];
    float* out = (float*)d_out;

    float *pT1, *pT2, *pT3, *pT4, *pHA, *pHB, *pU, *pY1, *pY2, *pY3, *pY4;
    cudaGetSymbolAddress((void**)&pT1, g_T1);
    cudaGetSymbolAddress((void**)&pT2, g_T2);
    cudaGetSymbolAddress((void**)&pT3, g_T3);
    cudaGetSymbolAddress((void**)&pT4, g_T4);
    cudaGetSymbolAddress((void**)&pHA, g_HA);
    cudaGetSymbolAddress((void**)&pHB, g_HB);
    cudaGetSymbolAddress((void**)&pU, g_U);
    cudaGetSymbolAddress((void**)&pY1, g_Y1);
    cudaGetSymbolAddress((void**)&pY2, g_Y2);
    cudaGetSymbolAddress((void**)&pY3, g_Y3);
    cudaGetSymbolAddress((void**)&pY4, g_Y4);

    detect_kernel<<<1, 256>>>((const int*)ei);
    init_kernel<<<NBLK, 256>>>();
    deg_kernel<<<(NE + 255) / 256, 256>>>(ei);
    dsum_kernel<<<NBLK, 256>>>();
    bscan_kernel<<<1, 256>>>();
    rowptr_kernel<<<NBLK, 256>>>();
    fill_kernel<<<(NE + 255) / 256, 256>>>(ei);
    wtilde_kernel<<<3, 256>>>(conv_w + (size_t)5 * 5 * W * W, lin_w);
    const_kernel<<<1, 32>>>(conv_b + 5 * W, lin_w, lin_b);

    const int GG = (NN + 127) / 128;

    // first 5 conv layers (all with relu)
    const float* Hin = x;
    float* Hout = pHA;
    for (int l = 0; l < 5; l++) {
        propagate_kernel<<<PROP_BLOCKS, 256>>>(Hin, nullptr, pT1, 0);
        propagate_kernel<<<PROP_BLOCKS, 256>>>(pT1, Hin, pT2, 1);
        propagate_kernel<<<PROP_BLOCKS, 256>>>(pT2, pT1, pT3, 1);
        propagate_kernel<<<PROP_BLOCKS, 256>>>(pT3, pT2, pT4, 1);
        Ptr5 T;
        T.p[0] = Hin; T.p[1] = pT1; T.p[2] = pT2; T.p[3] = pT3; T.p[4] = pT4;
        gemm5_mma_kernel<<<GG, 256>>>(T, conv_w + (size_t)l * 5 * W * W,
                                      conv_b + l * W, Hout, 1);
        Hin = Hout;
        Hout = (Hout == pHA) ? pHB : pHA;
    }

    // telescoped last layer
    u_kernel<<<(NN + 7) / 8, 256>>>(Hin, pU);
    prop8_kernel<<<PROP_BLOCKS, 256>>>(pU, nullptr, pY1, 0);
    prop8_kernel<<<PROP_BLOCKS, 256>>>(pY1, pU, pY2, 1);
    prop8_kernel<<<PROP_BLOCKS, 256>>>(pY2, pY1, pY3, 1);
    prop8_kernel<<<PROP_BLOCKS, 256>>>(pY3, pY2, pY4, 1);
    combine_kernel<<<(NN + 255) / 256, 256>>>(pU, pY1, pY2, pY3, pY4, out);
}